// round 3
// baseline (speedup 1.0000x reference)
#include <cuda_runtime.h>
#include <cuda_bf16.h>
#include <math.h>

#define BB 4
#define NN 4096
#define FF 128
#define SS 1024
#define KK 64
#define CC 256
#define MTOT (BB*SS*KK)
#define EPSF 1e-5f

// ---------------- device scratch ----------------
__device__ int   g_cent[BB*SS];
__device__ int   g_group[BB*SS*KK];
__device__ float g_P[BB*NN*CC];
__device__ float g_Q[BB*SS*CC];
__device__ float g_W1sumT[FF*CC];
__device__ float g_W1AT[FF*CC];
__device__ float g_W2T[CC*CC];
__device__ float g_sum1[CC], g_sq1[CC], g_sum2[CC], g_sq2[CC];
__device__ float g_mx[BB*SS*CC], g_mn[BB*SS*CC];

__device__ __forceinline__ float to_tf32(float x){
    unsigned u;
    asm("cvt.rna.tf32.f32 %0, %1;" : "=r"(u) : "f"(x));
    return __uint_as_float(u);
}

// ---------------- prep: weight transposes (TF32-rounded) + zero stats ----------------
__global__ void k_prep(const float* __restrict__ W1, const float* __restrict__ W2){
    int idx = blockIdx.x*256 + threadIdx.x;
    if (idx < FF*CC){
        int c = idx / CC, o = idx % CC;
        float a = to_tf32(W1[o*(2*FF)+c]);
        float bwt = to_tf32(W1[o*(2*FF)+FF+c]);
        g_W1sumT[idx] = a + bwt;     // matches ref's per-element tf32 rounding
        g_W1AT[idx]   = a;
    }
    if (idx < CC*CC){
        int c = idx / CC, o = idx % CC;
        g_W2T[idx] = to_tf32(W2[o*CC+c]);
    }
    if (idx < CC){
        g_sum1[idx]=0.f; g_sq1[idx]=0.f; g_sum2[idx]=0.f; g_sq2[idx]=0.f;
    }
}

// ---------------- FPS (deterministic, start idx 0) + sort ----------------
__global__ __launch_bounds__(1024) void k_fps(const float* __restrict__ pos){
    int b = blockIdx.x, t = threadIdx.x;
    const float* bp = pos + (size_t)b*NN*3;
    __shared__ float swv[32];
    __shared__ int   swi[32];
    __shared__ int   s_sel[SS];
    __shared__ unsigned s_mask[NN/32];
    __shared__ int   s_next;

    float px[4],py[4],pz[4],dd[4];
    float qx=bp[0], qy=bp[1], qz=bp[2];
#pragma unroll
    for (int j=0;j<4;j++){
        int i = t + j*1024;
        px[j]=bp[3*i]; py[j]=bp[3*i+1]; pz[j]=bp[3*i+2];
        float dx=px[j]-qx, dy=py[j]-qy, dz=pz[j]-qz;
        dd[j]=dx*dx+dy*dy+dz*dz;
    }
    if (t==0) s_sel[0]=0;

    for (int it=1; it<SS; it++){
        float bv=dd[0]; int bi=t;
#pragma unroll
        for (int j=1;j<4;j++){
            int i=t+j*1024;
            if (dd[j]>bv || (dd[j]==bv && i<bi)){ bv=dd[j]; bi=i; }
        }
        for (int off=16; off; off>>=1){
            float ov=__shfl_down_sync(0xffffffffu,bv,off);
            int   oi=__shfl_down_sync(0xffffffffu,bi,off);
            if (ov>bv || (ov==bv && oi<bi)){ bv=ov; bi=oi; }
        }
        if ((t&31)==0){ swv[t>>5]=bv; swi[t>>5]=bi; }
        __syncthreads();
        if (t<32){
            bv=swv[t]; bi=swi[t];
            for (int off=16; off; off>>=1){
                float ov=__shfl_down_sync(0xffffffffu,bv,off);
                int   oi=__shfl_down_sync(0xffffffffu,bi,off);
                if (ov>bv || (ov==bv && oi<bi)){ bv=ov; bi=oi; }
            }
            if (t==0){ s_next=bi; s_sel[it]=bi; }
        }
        __syncthreads();
        int nxt = s_next;
        float cx=bp[3*nxt], cy=bp[3*nxt+1], cz=bp[3*nxt+2];
#pragma unroll
        for (int j=0;j<4;j++){
            float dx=px[j]-cx, dy=py[j]-cy, dz=pz[j]-cz;
            float d = dx*dx+dy*dy+dz*dz;
            dd[j] = fminf(dd[j], d);
        }
    }
    __syncthreads();
    if (t < NN/32) s_mask[t]=0u;
    __syncthreads();
    if (t < SS) atomicOr(&s_mask[s_sel[t]>>5], 1u<<(s_sel[t]&31));
    __syncthreads();
    if (t < SS){
        int idx=s_sel[t];
        int w=idx>>5, r=0;
        for (int ww=0; ww<w; ww++) r += __popc(s_mask[ww]);
        r += __popc(s_mask[w] & ((1u<<(idx&31))-1u));
        g_cent[b*SS + r] = idx;
    }
}

// ---------------- KNN: exact fp32, 64 smallest via radix select ----------------
__global__ __launch_bounds__(128) void k_knn(const float* __restrict__ pos){
    __shared__ unsigned sbits[NN];
    __shared__ int shist[256];
    __shared__ unsigned s_prefix;
    __shared__ int s_want, s_cnt, s_eqcnt;
    __shared__ int s_eq[128];
    int q = blockIdx.x, t = threadIdx.x;
    int b = q / SS;
    int c = g_cent[q];
    const float* bp = pos + (size_t)b*NN*3;
    float qx=bp[3*c], qy=bp[3*c+1], qz=bp[3*c+2];
    float qq = __fadd_rn(__fadd_rn(__fmul_rn(qx,qx), __fmul_rn(qy,qy)), __fmul_rn(qz,qz));

    for (int i=t; i<NN; i+=128){
        float x=bp[3*i], y=bp[3*i+1], z=bp[3*i+2];
        float pp = __fadd_rn(__fadd_rn(__fmul_rn(x,x), __fmul_rn(y,y)), __fmul_rn(z,z));
        float dot = __fadd_rn(__fadd_rn(__fmul_rn(qx,x), __fmul_rn(qy,y)), __fmul_rn(qz,z));
        float d = __fadd_rn(__fadd_rn(__fmul_rn(-2.0f, dot), qq), pp);
        unsigned u = __float_as_uint(d);
        u = (u & 0x80000000u) ? ~u : (u | 0x80000000u);
        sbits[i] = u;
    }
    if (t==0){ s_prefix=0u; s_want=KK; s_cnt=0; s_eqcnt=0; }
    __syncthreads();

    for (int pass=0; pass<4; pass++){
        int shift = 24 - 8*pass;
        for (int i=t; i<256; i+=128) shist[i]=0;
        __syncthreads();
        unsigned pref = s_prefix;
        for (int i=t; i<NN; i+=128){
            unsigned u = sbits[i];
            bool m = (pass==0) || ((u >> (shift+8)) == pref);
            if (m) atomicAdd(&shist[(u>>shift)&0xFFu], 1);
        }
        __syncthreads();
        if (t==0){
            int want=s_want, cum=0, bin;
            for (bin=0; bin<256; bin++){
                int h=shist[bin];
                if (cum+h >= want) break;
                cum += h;
            }
            s_want = want - cum;
            s_prefix = (s_prefix<<8) | (unsigned)bin;
        }
        __syncthreads();
    }
    unsigned T = s_prefix;
    for (int i=t; i<NN; i+=128){
        unsigned u = sbits[i];
        if (u < T){
            int p = atomicAdd(&s_cnt,1);
            g_group[q*KK + p] = i;
        } else if (u == T){
            int p = atomicAdd(&s_eqcnt,1);
            if (p < 128) s_eq[p] = i;
        }
    }
    __syncthreads();
    if (t==0){
        int base = s_cnt;
        int nd   = KK - base;
        int ec   = s_eqcnt;
        if (ec <= 128){
            for (int r=0; r<nd; r++){
                int mi=r;
                for (int j=r+1; j<ec; j++) if (s_eq[j] < s_eq[mi]) mi=j;
                int tmp=s_eq[r]; s_eq[r]=s_eq[mi]; s_eq[mi]=tmp;
                g_group[q*KK + base + r] = s_eq[r];
            }
        } else {
            int w=nd, p=base;
            for (int i=0; i<NN && w>0; i++)
                if (sbits[i]==T){ g_group[q*KK + p++] = i; w--; }
        }
    }
}

// ---------------- P = tf32(feat) @ W1sumT  (B*N x 256, K=128) ----------------
__global__ __launch_bounds__(256) void k_pgemm(const float* __restrict__ feat){
    __shared__ float sf[16][FF];
    int r0 = blockIdx.x*16, t = threadIdx.x;
    for (int i=t; i<16*FF; i+=256)
        sf[i/FF][i%FF] = to_tf32(feat[(size_t)(r0 + i/FF)*FF + (i%FF)]);
    __syncthreads();
    int o = t;
    float acc[16];
#pragma unroll
    for (int r=0;r<16;r++) acc[r]=0.f;
    for (int c=0;c<FF;c++){
        float w = g_W1sumT[c*CC + o];
#pragma unroll
        for (int r=0;r<16;r++) acc[r]=fmaf(sf[r][c], w, acc[r]);
    }
#pragma unroll
    for (int r=0;r<16;r++) g_P[(size_t)(r0+r)*CC + o] = acc[r];
}

// ---------------- Q = tf32(centroid feat) @ W1AT  (B*S x 256) ----------------
__global__ __launch_bounds__(256) void k_qgemm(const float* __restrict__ feat){
    __shared__ float sf[16][FF];
    int r0 = blockIdx.x*16, t = threadIdx.x;
    for (int i=t; i<16*FF; i+=256){
        int rr = r0 + i/FF;
        int b  = rr / SS;
        int cent = g_cent[rr];
        sf[i/FF][i%FF] = to_tf32(feat[(size_t)(b*NN + cent)*FF + (i%FF)]);
    }
    __syncthreads();
    int o = t;
    float acc[16];
#pragma unroll
    for (int r=0;r<16;r++) acc[r]=0.f;
    for (int c=0;c<FF;c++){
        float w = g_W1AT[c*CC + o];
#pragma unroll
        for (int r=0;r<16;r++) acc[r]=fmaf(sf[r][c], w, acc[r]);
    }
#pragma unroll
    for (int r=0;r<16;r++) g_Q[(size_t)(r0+r)*CC + o] = acc[r];
}

// ---------------- BN1 stats ----------------
__global__ __launch_bounds__(256) void k_stats1(const float* __restrict__ b1){
    __shared__ int sg[KK];
    int q = blockIdx.x, t = threadIdx.x, b = q/SS;
    if (t < KK) sg[t] = g_group[q*KK + t];
    __syncthreads();
    int o = t;
    float base = b1[o] - g_Q[(size_t)q*CC + o];
    float sum=0.f, sq=0.f;
    for (int k=0;k<KK;k++){
        float h = g_P[(size_t)(b*NN + sg[k])*CC + o] + base;
        sum += h; sq = fmaf(h,h,sq);
    }
    atomicAdd(&g_sum1[o], sum);
    atomicAdd(&g_sq1[o],  sq);
}

// ---------------- layer2 GEMM (TF32-emulated) + fused BN1/ReLU + epilogue ----------------
extern __shared__ float sxT[];   // [CC][68]
__global__ __launch_bounds__(256) void k_gemm2(const float* __restrict__ b1,
                                               const float* __restrict__ gamma1,
                                               const float* __restrict__ beta1,
                                               const float* __restrict__ b2){
    __shared__ int sg[KK];
    int q = blockIdx.x, t = threadIdx.x, b = q/SS;
    if (t < KK) sg[t] = g_group[q*KK + t];
    __syncthreads();
    {   // build xT[c][k] = tf32(relu(BN1(h1)))
        int c = t;
        float mean = g_sum1[c]*(1.0f/MTOT);
        float var  = g_sq1[c]*(1.0f/MTOT) - mean*mean;
        float a    = gamma1[c]*rsqrtf(var + EPSF);
        float cc   = beta1[c] - mean*a;
        float dd   = fmaf(a, b1[c] - g_Q[(size_t)q*CC + c], cc);
        float* row = &sxT[c*68];
        for (int k=0;k<KK;k++){
            float p = g_P[(size_t)(b*NN + sg[k])*CC + c];
            row[k] = to_tf32(fmaxf(fmaf(a, p, dd), 0.f));
        }
    }
    __syncthreads();
    int o = t;
    float acc[KK];
#pragma unroll
    for (int k=0;k<KK;k++) acc[k]=0.f;
#pragma unroll 1
    for (int c=0;c<CC;c++){
        float w = g_W2T[c*CC + o];
        const float4* xr = reinterpret_cast<const float4*>(&sxT[c*68]);
#pragma unroll
        for (int k4=0;k4<KK/4;k4++){
            float4 v = xr[k4];
            acc[4*k4+0]=fmaf(v.x,w,acc[4*k4+0]);
            acc[4*k4+1]=fmaf(v.y,w,acc[4*k4+1]);
            acc[4*k4+2]=fmaf(v.z,w,acc[4*k4+2]);
            acc[4*k4+3]=fmaf(v.w,w,acc[4*k4+3]);
        }
    }
    float bias=b2[o];
    float mx=-3.402823466e38f, mn=3.402823466e38f, sum=0.f, sq=0.f;
#pragma unroll
    for (int k=0;k<KK;k++){
        float h = acc[k] + bias;
        mx=fmaxf(mx,h); mn=fminf(mn,h);
        sum += h; sq = fmaf(h,h,sq);
    }
    g_mx[(size_t)q*CC+o]=mx;
    g_mn[(size_t)q*CC+o]=mn;
    atomicAdd(&g_sum2[o], sum);
    atomicAdd(&g_sq2[o],  sq);
}

// ---------------- BN2 + ReLU + maxpool + outputs ----------------
__global__ __launch_bounds__(256) void k_out(const float* __restrict__ pos,
                                             const float* __restrict__ gamma2,
                                             const float* __restrict__ beta2,
                                             float* __restrict__ out){
    int q = blockIdx.x, t = threadIdx.x, b = q/SS;
    int o = t;
    float mean = g_sum2[o]*(1.0f/MTOT);
    float var  = g_sq2[o]*(1.0f/MTOT) - mean*mean;
    float a    = gamma2[o]*rsqrtf(var + EPSF);
    float cc   = beta2[o] - mean*a;
    float v = (a>=0.f) ? fmaf(a, g_mx[(size_t)q*CC+o], cc)
                       : fmaf(a, g_mn[(size_t)q*CC+o], cc);
    out[(size_t)BB*SS*3 + (size_t)q*CC + o] = fmaxf(v, 0.f);
    if (t < 3){
        int cent = g_cent[q];
        out[(size_t)q*3 + t] = pos[(size_t)(b*NN + cent)*3 + t];
    }
}

// ---------------- launch ----------------
extern "C" void kernel_launch(void* const* d_in, const int* in_sizes, int n_in,
                              void* d_out, int out_size){
    const float* pos    = (const float*)d_in[0];
    const float* feat   = (const float*)d_in[1];
    const float* W1     = (const float*)d_in[2];
    const float* b1     = (const float*)d_in[3];
    const float* gamma1 = (const float*)d_in[4];
    const float* beta1  = (const float*)d_in[5];
    const float* W2     = (const float*)d_in[6];
    const float* b2     = (const float*)d_in[7];
    const float* gamma2 = (const float*)d_in[8];
    const float* beta2  = (const float*)d_in[9];
    float* out = (float*)d_out;

    cudaFuncSetAttribute(k_gemm2, cudaFuncAttributeMaxDynamicSharedMemorySize, 72*1024);

    k_prep  <<<256, 256>>>(W1, W2);
    k_fps   <<<BB, 1024>>>(pos);
    k_knn   <<<BB*SS, 128>>>(pos);
    k_pgemm <<<(BB*NN)/16, 256>>>(feat);
    k_qgemm <<<(BB*SS)/16, 256>>>(feat);
    k_stats1<<<BB*SS, 256>>>(b1);
    k_gemm2 <<<BB*SS, 256, CC*68*sizeof(float)>>>(b1, gamma1, beta1, b2);
    k_out   <<<BB*SS, 256>>>(pos, gamma2, beta2, out);
}

// round 5
// speedup vs baseline: 1.5770x; 1.5770x over previous
#include <cuda_runtime.h>
#include <cuda_bf16.h>
#include <math.h>
#include <stdint.h>

#define BB 4
#define NN 4096
#define FF 128
#define SS 1024
#define KK 64
#define CC 256
#define MTOT (BB*SS*KK)
#define EPSF 1e-5f

// ---------------- device scratch ----------------
__device__ int   g_cent[BB*SS];
__device__ int   g_group[BB*SS*KK];
__device__ float g_P[BB*NN*CC];
__device__ float g_Q[BB*SS*CC];
__device__ float g_W1sumT[FF*CC];
__device__ float g_W1AT[FF*CC];
__device__ float g_W2rt[CC*CC];          // tf32-rounded W2, [o][c] row-major
__device__ float g_sum1[CC], g_sq1[CC], g_sum2[CC], g_sq2[CC];
__device__ float g_mx[BB*SS*CC], g_mn[BB*SS*CC];

__device__ __forceinline__ float to_tf32(float x){
    unsigned u;
    asm("cvt.rna.tf32.f32 %0, %1;" : "=r"(u) : "f"(x));
    return __uint_as_float(u);
}

// ---------------- prep ----------------
__global__ void k_prep(const float* __restrict__ W1, const float* __restrict__ W2){
    int idx = blockIdx.x*256 + threadIdx.x;
    if (idx < FF*CC){
        int c = idx / CC, o = idx % CC;
        float a = to_tf32(W1[o*(2*FF)+c]);
        float bwt = to_tf32(W1[o*(2*FF)+FF+c]);
        g_W1sumT[idx] = a + bwt;
        g_W1AT[idx]   = a;
    }
    if (idx < CC*CC){
        g_W2rt[idx] = to_tf32(W2[idx]);
    }
    if (idx < CC){
        g_sum1[idx]=0.f; g_sq1[idx]=0.f; g_sum2[idx]=0.f; g_sq2[idx]=0.f;
    }
}

// ---------------- FPS ----------------
__global__ __launch_bounds__(1024) void k_fps(const float* __restrict__ pos){
    int b = blockIdx.x, t = threadIdx.x;
    const float* bp = pos + (size_t)b*NN*3;
    __shared__ float swv[32];
    __shared__ int   swi[32];
    __shared__ int   s_sel[SS];
    __shared__ unsigned s_mask[NN/32];
    __shared__ int   s_next;

    float px[4],py[4],pz[4],dd[4];
    float qx=bp[0], qy=bp[1], qz=bp[2];
#pragma unroll
    for (int j=0;j<4;j++){
        int i = t + j*1024;
        px[j]=bp[3*i]; py[j]=bp[3*i+1]; pz[j]=bp[3*i+2];
        float dx=px[j]-qx, dy=py[j]-qy, dz=pz[j]-qz;
        dd[j]=dx*dx+dy*dy+dz*dz;
    }
    if (t==0) s_sel[0]=0;

    for (int it=1; it<SS; it++){
        float bv=dd[0]; int bi=t;
#pragma unroll
        for (int j=1;j<4;j++){
            int i=t+j*1024;
            if (dd[j]>bv || (dd[j]==bv && i<bi)){ bv=dd[j]; bi=i; }
        }
        for (int off=16; off; off>>=1){
            float ov=__shfl_down_sync(0xffffffffu,bv,off);
            int   oi=__shfl_down_sync(0xffffffffu,bi,off);
            if (ov>bv || (ov==bv && oi<bi)){ bv=ov; bi=oi; }
        }
        if ((t&31)==0){ swv[t>>5]=bv; swi[t>>5]=bi; }
        __syncthreads();
        if (t<32){
            bv=swv[t]; bi=swi[t];
            for (int off=16; off; off>>=1){
                float ov=__shfl_down_sync(0xffffffffu,bv,off);
                int   oi=__shfl_down_sync(0xffffffffu,bi,off);
                if (ov>bv || (ov==bv && oi<bi)){ bv=ov; bi=oi; }
            }
            if (t==0){ s_next=bi; s_sel[it]=bi; }
        }
        __syncthreads();
        int nxt = s_next;
        float cx=bp[3*nxt], cy=bp[3*nxt+1], cz=bp[3*nxt+2];
#pragma unroll
        for (int j=0;j<4;j++){
            float dx=px[j]-cx, dy=py[j]-cy, dz=pz[j]-cz;
            float d = dx*dx+dy*dy+dz*dz;
            dd[j] = fminf(dd[j], d);
        }
    }
    __syncthreads();
    if (t < NN/32) s_mask[t]=0u;
    __syncthreads();
    if (t < SS) atomicOr(&s_mask[s_sel[t]>>5], 1u<<(s_sel[t]&31));
    __syncthreads();
    if (t < SS){
        int idx=s_sel[t];
        int w=idx>>5, r=0;
        for (int ww=0; ww<w; ww++) r += __popc(s_mask[ww]);
        r += __popc(s_mask[w] & ((1u<<(idx&31))-1u));
        g_cent[b*SS + r] = idx;
    }
}

// ---------------- KNN (exact fp32 radix select) ----------------
__global__ __launch_bounds__(128) void k_knn(const float* __restrict__ pos){
    __shared__ unsigned sbits[NN];
    __shared__ int shist[256];
    __shared__ unsigned s_prefix;
    __shared__ int s_want, s_cnt, s_eqcnt;
    __shared__ int s_eq[128];
    int q = blockIdx.x, t = threadIdx.x;
    int b = q / SS;
    int c = g_cent[q];
    const float* bp = pos + (size_t)b*NN*3;
    float qx=bp[3*c], qy=bp[3*c+1], qz=bp[3*c+2];
    float qq = __fadd_rn(__fadd_rn(__fmul_rn(qx,qx), __fmul_rn(qy,qy)), __fmul_rn(qz,qz));

    for (int i=t; i<NN; i+=128){
        float x=bp[3*i], y=bp[3*i+1], z=bp[3*i+2];
        float pp = __fadd_rn(__fadd_rn(__fmul_rn(x,x), __fmul_rn(y,y)), __fmul_rn(z,z));
        float dot = __fadd_rn(__fadd_rn(__fmul_rn(qx,x), __fmul_rn(qy,y)), __fmul_rn(qz,z));
        float d = __fadd_rn(__fadd_rn(__fmul_rn(-2.0f, dot), qq), pp);
        unsigned u = __float_as_uint(d);
        u = (u & 0x80000000u) ? ~u : (u | 0x80000000u);
        sbits[i] = u;
    }
    if (t==0){ s_prefix=0u; s_want=KK; s_cnt=0; s_eqcnt=0; }
    __syncthreads();

    for (int pass=0; pass<4; pass++){
        int shift = 24 - 8*pass;
        for (int i=t; i<256; i+=128) shist[i]=0;
        __syncthreads();
        unsigned pref = s_prefix;
        for (int i=t; i<NN; i+=128){
            unsigned u = sbits[i];
            bool m = (pass==0) || ((u >> (shift+8)) == pref);
            if (m) atomicAdd(&shist[(u>>shift)&0xFFu], 1);
        }
        __syncthreads();
        if (t==0){
            int want=s_want, cum=0, bin;
            for (bin=0; bin<256; bin++){
                int h=shist[bin];
                if (cum+h >= want) break;
                cum += h;
            }
            s_want = want - cum;
            s_prefix = (s_prefix<<8) | (unsigned)bin;
        }
        __syncthreads();
    }
    unsigned T = s_prefix;
    for (int i=t; i<NN; i+=128){
        unsigned u = sbits[i];
        if (u < T){
            int p = atomicAdd(&s_cnt,1);
            g_group[q*KK + p] = i;
        } else if (u == T){
            int p = atomicAdd(&s_eqcnt,1);
            if (p < 128) s_eq[p] = i;
        }
    }
    __syncthreads();
    if (t==0){
        int base = s_cnt;
        int nd   = KK - base;
        int ec   = s_eqcnt;
        if (ec <= 128){
            for (int r=0; r<nd; r++){
                int mi=r;
                for (int j=r+1; j<ec; j++) if (s_eq[j] < s_eq[mi]) mi=j;
                int tmp=s_eq[r]; s_eq[r]=s_eq[mi]; s_eq[mi]=tmp;
                g_group[q*KK + base + r] = s_eq[r];
            }
        } else {
            int w=nd, p=base;
            for (int i=0; i<NN && w>0; i++)
                if (sbits[i]==T){ g_group[q*KK + p++] = i; w--; }
        }
    }
}

// ---------------- P = tf32(feat) @ W1sumT ----------------
__global__ __launch_bounds__(256) void k_pgemm(const float* __restrict__ feat){
    __shared__ float sf[16][FF];
    int r0 = blockIdx.x*16, t = threadIdx.x;
    for (int i=t; i<16*FF; i+=256)
        sf[i/FF][i%FF] = to_tf32(feat[(size_t)(r0 + i/FF)*FF + (i%FF)]);
    __syncthreads();
    int o = t;
    float acc[16];
#pragma unroll
    for (int r=0;r<16;r++) acc[r]=0.f;
    for (int c=0;c<FF;c++){
        float w = g_W1sumT[c*CC + o];
#pragma unroll
        for (int r=0;r<16;r++) acc[r]=fmaf(sf[r][c], w, acc[r]);
    }
#pragma unroll
    for (int r=0;r<16;r++) g_P[(size_t)(r0+r)*CC + o] = acc[r];
}

// ---------------- Q = tf32(centroid feat) @ W1AT ----------------
__global__ __launch_bounds__(256) void k_qgemm(const float* __restrict__ feat){
    __shared__ float sf[16][FF];
    int r0 = blockIdx.x*16, t = threadIdx.x;
    for (int i=t; i<16*FF; i+=256){
        int rr = r0 + i/FF;
        int b  = rr / SS;
        int cent = g_cent[rr];
        sf[i/FF][i%FF] = to_tf32(feat[(size_t)(b*NN + cent)*FF + (i%FF)]);
    }
    __syncthreads();
    int o = t;
    float acc[16];
#pragma unroll
    for (int r=0;r<16;r++) acc[r]=0.f;
    for (int c=0;c<FF;c++){
        float w = g_W1AT[c*CC + o];
#pragma unroll
        for (int r=0;r<16;r++) acc[r]=fmaf(sf[r][c], w, acc[r]);
    }
#pragma unroll
    for (int r=0;r<16;r++) g_Q[(size_t)(r0+r)*CC + o] = acc[r];
}

// ---------------- BN1 stats ----------------
__global__ __launch_bounds__(256) void k_stats1(const float* __restrict__ b1){
    __shared__ int sg[KK];
    int q = blockIdx.x, t = threadIdx.x, b = q/SS;
    if (t < KK) sg[t] = g_group[q*KK + t];
    __syncthreads();
    int o = t;
    float base = b1[o] - g_Q[(size_t)q*CC + o];
    float sum=0.f, sq=0.f;
    for (int k=0;k<KK;k++){
        float h = g_P[(size_t)(b*NN + sg[k])*CC + o] + base;
        sum += h; sq = fmaf(h,h,sq);
    }
    atomicAdd(&g_sum1[o], sum);
    atomicAdd(&g_sq1[o],  sq);
}

// ---------------- layer2 GEMM via mma.sync tf32 (legacy HMMA, arch-neutral) ----------------
// CTA: M=128 (2 groups x 64 nbrs), N=256 outputs, K=256 in 8 chunks of 32.
// Warps: 2(M) x 4(N); warp tile 64x64 = 4x8 m16n8k8 tiles.
#define ASTR 36
extern __shared__ float dyn_smem[];
__global__ __launch_bounds__(256, 1) void k_gemm2m(const float* __restrict__ b1,
                                                   const float* __restrict__ gamma1,
                                                   const float* __restrict__ beta1,
                                                   const float* __restrict__ b2){
    __shared__ float a_s[CC];
    __shared__ float d_s[2*CC];
    __shared__ int   s_nbr[128];

    float* As = dyn_smem;             // [128][ASTR]
    float* Bs = dyn_smem + 128*ASTR;  // [256][ASTR]

    int t = threadIdx.x;
    int bid = blockIdx.x;
    int q0 = 2*bid;
    int batch = q0 >> 10;

    if (t < 128) s_nbr[t] = g_group[bid*128 + t];
    {
        int c = t;
        float mean = g_sum1[c]*(1.0f/MTOT);
        float var  = g_sq1[c]*(1.0f/MTOT) - mean*mean;
        float a    = gamma1[c]*rsqrtf(var + EPSF);
        float ccv  = beta1[c] - mean*a;
        a_s[c] = a;
        d_s[c]    = fmaf(a, b1[c] - g_Q[(size_t)q0*CC + c], ccv);
        d_s[CC+c] = fmaf(a, b1[c] - g_Q[(size_t)(q0+1)*CC + c], ccv);
    }

    int lane = t & 31, wid = t >> 5;
    int warpM = wid >> 2, warpN = wid & 3;
    int r0 = warpM*64, n0 = warpN*64;
    int g = lane >> 2, tig = lane & 3;

    float acc[4][8][4];
#pragma unroll
    for (int mt=0;mt<4;mt++)
#pragma unroll
        for (int nt=0;nt<8;nt++)
#pragma unroll
            for (int i=0;i<4;i++) acc[mt][nt][i]=0.f;

    const uint32_t* Ab = (const uint32_t*)As + (r0+g)*ASTR + tig;
    const uint32_t* Bb = (const uint32_t*)Bs + (n0+g)*ASTR + tig;

    // A-build addressing: 2 threads per row
    int am = t >> 1;
    int aj0 = (t & 1) * 16;
    int agrp = am >> 6;
    const float* Pr_base = g_P + ((size_t)(batch*NN)) * CC;
    __syncthreads();
    int nbr = s_nbr[am];
    const float* Pr = Pr_base + (size_t)nbr*CC;

#pragma unroll 1
    for (int kc=0; kc<8; kc++){
        if (kc > 0) __syncthreads();   // prior chunk's mma reads done
        // ---- build A chunk (gather + BN1 + ReLU + tf32) ----
        {
            const float* dv = d_s + agrp*CC + kc*32 + aj0;
            const float* av = a_s + kc*32 + aj0;
            const float* pr = Pr + kc*32 + aj0;
            float* arow = As + am*ASTR + aj0;
#pragma unroll
            for (int i=0;i<4;i++){
                float4 p = *(const float4*)(pr + 4*i);
                float4 v;
                v.x = to_tf32(fmaxf(fmaf(av[4*i+0], p.x, dv[4*i+0]), 0.f));
                v.y = to_tf32(fmaxf(fmaf(av[4*i+1], p.y, dv[4*i+1]), 0.f));
                v.z = to_tf32(fmaxf(fmaf(av[4*i+2], p.z, dv[4*i+2]), 0.f));
                v.w = to_tf32(fmaxf(fmaf(av[4*i+3], p.w, dv[4*i+3]), 0.f));
                *(float4*)(arow + 4*i) = v;
            }
        }
        // ---- build B chunk from pre-rounded W2 ----
        {
            const float* wr = g_W2rt + (size_t)t*CC + kc*32;
            float* brow = Bs + t*ASTR;
#pragma unroll
            for (int i=0;i<8;i++)
                *(float4*)(brow + 4*i) = *(const float4*)(wr + 4*i);
        }
        __syncthreads();
        // ---- mma: 4 k-steps of 8 ----
#pragma unroll
        for (int kk=0; kk<4; kk++){
            int kb = kk*8;
            uint32_t af[4][4];
#pragma unroll
            for (int mt=0;mt<4;mt++){
                af[mt][0] = Ab[(mt*16    )*ASTR + kb];
                af[mt][1] = Ab[(mt*16 + 8)*ASTR + kb];
                af[mt][2] = Ab[(mt*16    )*ASTR + kb + 4];
                af[mt][3] = Ab[(mt*16 + 8)*ASTR + kb + 4];
            }
            uint32_t bf[8][2];
#pragma unroll
            for (int nt=0;nt<8;nt++){
                bf[nt][0] = Bb[(nt*8)*ASTR + kb];
                bf[nt][1] = Bb[(nt*8)*ASTR + kb + 4];
            }
#pragma unroll
            for (int mt=0;mt<4;mt++){
#pragma unroll
                for (int nt=0;nt<8;nt++){
                    asm volatile(
                        "mma.sync.aligned.m16n8k8.row.col.f32.tf32.tf32.f32 "
                        "{%0,%1,%2,%3}, {%4,%5,%6,%7}, {%8,%9}, {%0,%1,%2,%3};"
                        : "+f"(acc[mt][nt][0]), "+f"(acc[mt][nt][1]),
                          "+f"(acc[mt][nt][2]), "+f"(acc[mt][nt][3])
                        : "r"(af[mt][0]), "r"(af[mt][1]), "r"(af[mt][2]), "r"(af[mt][3]),
                          "r"(bf[nt][0]), "r"(bf[nt][1]));
                }
            }
        }
    }

    // ---- epilogue: per-column bias + max/min/sum/sq over this warp's 64 rows (one group) ----
    int q = q0 + warpM;
#pragma unroll
    for (int nt=0; nt<8; nt++){
#pragma unroll
        for (int hc=0; hc<2; hc++){
            int col = n0 + nt*8 + 2*tig + hc;
            float bias = __ldg(&b2[col]);
            float mx=-3.402823466e38f, mn=3.402823466e38f, sum=0.f, sq=0.f;
#pragma unroll
            for (int mt=0;mt<4;mt++){
                float h0 = acc[mt][nt][hc]   + bias;
                float h1 = acc[mt][nt][2+hc] + bias;
                mx=fmaxf(mx,fmaxf(h0,h1)); mn=fminf(mn,fminf(h0,h1));
                sum += h0 + h1; sq = fmaf(h0,h0,sq); sq = fmaf(h1,h1,sq);
            }
#pragma unroll
            for (int off=4; off<=16; off<<=1){
                mx  = fmaxf(mx,  __shfl_xor_sync(0xffffffffu, mx,  off));
                mn  = fminf(mn,  __shfl_xor_sync(0xffffffffu, mn,  off));
                sum = sum +      __shfl_xor_sync(0xffffffffu, sum, off);
                sq  = sq +       __shfl_xor_sync(0xffffffffu, sq,  off);
            }
            if (g == 0){
                g_mx[(size_t)q*CC + col] = mx;
                g_mn[(size_t)q*CC + col] = mn;
                atomicAdd(&g_sum2[col], sum);
                atomicAdd(&g_sq2[col],  sq);
            }
        }
    }
}

// ---------------- BN2 + ReLU + maxpool + outputs ----------------
__global__ __launch_bounds__(256) void k_out(const float* __restrict__ pos,
                                             const float* __restrict__ gamma2,
                                             const float* __restrict__ beta2,
                                             float* __restrict__ out){
    int q = blockIdx.x, t = threadIdx.x, b = q/SS;
    int o = t;
    float mean = g_sum2[o]*(1.0f/MTOT);
    float var  = g_sq2[o]*(1.0f/MTOT) - mean*mean;
    float a    = gamma2[o]*rsqrtf(var + EPSF);
    float cc   = beta2[o] - mean*a;
    float v = (a>=0.f) ? fmaf(a, g_mx[(size_t)q*CC+o], cc)
                       : fmaf(a, g_mn[(size_t)q*CC+o], cc);
    out[(size_t)BB*SS*3 + (size_t)q*CC + o] = fmaxf(v, 0.f);
    if (t < 3){
        int cent = g_cent[q];
        out[(size_t)q*3 + t] = pos[(size_t)(b*NN + cent)*3 + t];
    }
}

// ---------------- launch ----------------
extern "C" void kernel_launch(void* const* d_in, const int* in_sizes, int n_in,
                              void* d_out, int out_size){
    const float* pos    = (const float*)d_in[0];
    const float* feat   = (const float*)d_in[1];
    const float* W1     = (const float*)d_in[2];
    const float* b1     = (const float*)d_in[3];
    const float* gamma1 = (const float*)d_in[4];
    const float* beta1  = (const float*)d_in[5];
    const float* W2     = (const float*)d_in[6];
    const float* b2     = (const float*)d_in[7];
    const float* gamma2 = (const float*)d_in[8];
    const float* beta2  = (const float*)d_in[9];
    float* out = (float*)d_out;

    const int gemm2_smem = (128 + 256) * ASTR * sizeof(float);  // 55296 B
    cudaFuncSetAttribute(k_gemm2m, cudaFuncAttributeMaxDynamicSharedMemorySize, gemm2_smem);

    k_prep  <<<256, 256>>>(W1, W2);
    k_fps   <<<BB, 1024>>>(pos);
    k_knn   <<<BB*SS, 128>>>(pos);
    k_pgemm <<<(BB*NN)/16, 256>>>(feat);
    k_qgemm <<<(BB*SS)/16, 256>>>(feat);
    k_stats1<<<BB*SS, 256>>>(b1);
    k_gemm2m<<<BB*SS/2, 256, gemm2_smem>>>(b1, gamma1, beta1, b2);
    k_out   <<<BB*SS, 256>>>(pos, gamma2, beta2, out);
}

// round 6
// speedup vs baseline: 1.8253x; 1.1575x over previous
#include <cuda_runtime.h>
#include <cuda_bf16.h>
#include <math.h>
#include <stdint.h>

#define BB 4
#define NN 4096
#define FF 128
#define SS 1024
#define KK 64
#define CC 256
#define MTOT (BB*SS*KK)
#define EPSF 1e-5f

// ---------------- device scratch ----------------
__device__ int   g_cent[BB*SS];
__device__ int   g_group[BB*SS*KK];
__device__ float g_P[BB*NN*CC];
__device__ float g_Q[BB*SS*CC];
__device__ float g_W1sumT[FF*CC];
__device__ float g_W1AT[FF*CC];
__device__ float g_W2rt[CC*CC];
__device__ float g_sum1[CC], g_sq1[CC], g_sum2[CC], g_sq2[CC];
__device__ float g_mx[BB*SS*CC], g_mn[BB*SS*CC];

__device__ __forceinline__ float to_tf32(float x){
    unsigned u;
    asm("cvt.rna.tf32.f32 %0, %1;" : "=r"(u) : "f"(x));
    return __uint_as_float(u);
}

// ---------------- prep ----------------
__global__ void k_prep(const float* __restrict__ W1, const float* __restrict__ W2){
    int idx = blockIdx.x*256 + threadIdx.x;
    if (idx < FF*CC){
        int c = idx / CC, o = idx % CC;
        float a = to_tf32(W1[o*(2*FF)+c]);
        float bwt = to_tf32(W1[o*(2*FF)+FF+c]);
        g_W1sumT[idx] = a + bwt;
        g_W1AT[idx]   = a;
    }
    if (idx < CC*CC){
        g_W2rt[idx] = to_tf32(W2[idx]);
    }
    if (idx < CC){
        g_sum1[idx]=0.f; g_sq1[idx]=0.f; g_sum2[idx]=0.f; g_sq2[idx]=0.f;
    }
}

// ---------------- FPS: 256 threads, 16 pts/thread, 1 barrier/iter ----------------
__global__ __launch_bounds__(256) void k_fps(const float* __restrict__ pos){
    int b = blockIdx.x, t = threadIdx.x;
    const float* bp = pos + (size_t)b*NN*3;
    __shared__ uint2 swred[2][8];        // [parity][warp] = (distbits, idx)
    __shared__ int   s_sel[SS];
    __shared__ unsigned s_mask[NN/32];

    float px[16],py[16],pz[16],dd[16];
    float qx=bp[0], qy=bp[1], qz=bp[2];
#pragma unroll
    for (int j=0;j<16;j++){
        int i = t + 256*j;
        px[j]=bp[3*i]; py[j]=bp[3*i+1]; pz[j]=bp[3*i+2];
        float dx=px[j]-qx, dy=py[j]-qy, dz=pz[j]-qz;
        dd[j]=dx*dx+dy*dy+dz*dz;
    }
    if (t==0) s_sel[0]=0;

    int wid = t >> 5;
#pragma unroll 1
    for (int it=1; it<SS; it++){
        // scan current dd: per-thread argmax, first-index tie-break (j ascending = idx ascending)
        float bv=dd[0]; int bi=t;
#pragma unroll
        for (int j=1;j<16;j++){
            if (dd[j] > bv){ bv=dd[j]; bi=t+256*j; }
        }
        // warp reduce: distances >= 0 so float bits are order-monotone
        unsigned ub = __float_as_uint(bv);
        unsigned rv = __reduce_max_sync(0xffffffffu, ub);
        unsigned mi = (ub==rv) ? (unsigned)bi : 0xffffffffu;
        unsigned ri = __reduce_min_sync(0xffffffffu, mi);
        if ((t&31)==0) swred[it&1][wid] = make_uint2(rv, ri);
        __syncthreads();
        // all threads: reduce 8 warp entries (deterministic min-index tie-break)
        uint2 best = swred[it&1][0];
#pragma unroll
        for (int w=1; w<8; w++){
            uint2 e = swred[it&1][w];
            if (e.x > best.x || (e.x == best.x && e.y < best.y)) best = e;
        }
        int nxt = (int)best.y;
        if (t==0) s_sel[it] = nxt;
        float cx=__ldg(bp+3*nxt), cy=__ldg(bp+3*nxt+1), cz=__ldg(bp+3*nxt+2);
#pragma unroll
        for (int j=0;j<16;j++){
            float dx=px[j]-cx, dy=py[j]-cy, dz=pz[j]-cz;
            float d = dx*dx+dy*dy+dz*dz;
            dd[j] = fminf(dd[j], d);
        }
    }
    __syncthreads();
    // sort selected indices ascending via bitmask ranks
    if (t < NN/32) s_mask[t]=0u;
    __syncthreads();
    for (int i=t; i<SS; i+=256) atomicOr(&s_mask[s_sel[i]>>5], 1u<<(s_sel[i]&31));
    __syncthreads();
    for (int i=t; i<SS; i+=256){
        int idx=s_sel[i];
        int w=idx>>5, r=0;
        for (int ww=0; ww<w; ww++) r += __popc(s_mask[ww]);
        r += __popc(s_mask[w] & ((1u<<(idx&31))-1u));
        g_cent[b*SS + r] = idx;
    }
}

// ---------------- KNN (exact fp32 radix select) ----------------
__global__ __launch_bounds__(128) void k_knn(const float* __restrict__ pos){
    __shared__ unsigned sbits[NN];
    __shared__ int shist[256];
    __shared__ unsigned s_prefix;
    __shared__ int s_want, s_cnt, s_eqcnt;
    __shared__ int s_eq[128];
    int q = blockIdx.x, t = threadIdx.x;
    int b = q / SS;
    int c = g_cent[q];
    const float* bp = pos + (size_t)b*NN*3;
    float qx=bp[3*c], qy=bp[3*c+1], qz=bp[3*c+2];
    float qq = __fadd_rn(__fadd_rn(__fmul_rn(qx,qx), __fmul_rn(qy,qy)), __fmul_rn(qz,qz));

    for (int i=t; i<NN; i+=128){
        float x=bp[3*i], y=bp[3*i+1], z=bp[3*i+2];
        float pp = __fadd_rn(__fadd_rn(__fmul_rn(x,x), __fmul_rn(y,y)), __fmul_rn(z,z));
        float dot = __fadd_rn(__fadd_rn(__fmul_rn(qx,x), __fmul_rn(qy,y)), __fmul_rn(qz,z));
        float d = __fadd_rn(__fadd_rn(__fmul_rn(-2.0f, dot), qq), pp);
        unsigned u = __float_as_uint(d);
        u = (u & 0x80000000u) ? ~u : (u | 0x80000000u);
        sbits[i] = u;
    }
    if (t==0){ s_prefix=0u; s_want=KK; s_cnt=0; s_eqcnt=0; }
    __syncthreads();

    for (int pass=0; pass<4; pass++){
        int shift = 24 - 8*pass;
        for (int i=t; i<256; i+=128) shist[i]=0;
        __syncthreads();
        unsigned pref = s_prefix;
        for (int i=t; i<NN; i+=128){
            unsigned u = sbits[i];
            bool m = (pass==0) || ((u >> (shift+8)) == pref);
            if (m) atomicAdd(&shist[(u>>shift)&0xFFu], 1);
        }
        __syncthreads();
        if (t==0){
            int want=s_want, cum=0, bin;
            for (bin=0; bin<256; bin++){
                int h=shist[bin];
                if (cum+h >= want) break;
                cum += h;
            }
            s_want = want - cum;
            s_prefix = (s_prefix<<8) | (unsigned)bin;
        }
        __syncthreads();
    }
    unsigned T = s_prefix;
    for (int i=t; i<NN; i+=128){
        unsigned u = sbits[i];
        if (u < T){
            int p = atomicAdd(&s_cnt,1);
            g_group[q*KK + p] = i;
        } else if (u == T){
            int p = atomicAdd(&s_eqcnt,1);
            if (p < 128) s_eq[p] = i;
        }
    }
    __syncthreads();
    if (t==0){
        int base = s_cnt;
        int nd   = KK - base;
        int ec   = s_eqcnt;
        if (ec <= 128){
            for (int r=0; r<nd; r++){
                int mi=r;
                for (int j=r+1; j<ec; j++) if (s_eq[j] < s_eq[mi]) mi=j;
                int tmp=s_eq[r]; s_eq[r]=s_eq[mi]; s_eq[mi]=tmp;
                g_group[q*KK + base + r] = s_eq[r];
            }
        } else {
            int w=nd, p=base;
            for (int i=0; i<NN && w>0; i++)
                if (sbits[i]==T){ g_group[q*KK + p++] = i; w--; }
        }
    }
}

// ---------------- P = tf32(feat) @ W1sumT  (row-offset param for split launch) ----------------
__global__ __launch_bounds__(256) void k_pgemm(const float* __restrict__ feat, int blk0){
    __shared__ float sf[16][FF];
    int r0 = (blk0 + blockIdx.x)*16, t = threadIdx.x;
    for (int i=t; i<16*FF; i+=256)
        sf[i/FF][i%FF] = to_tf32(feat[(size_t)(r0 + i/FF)*FF + (i%FF)]);
    __syncthreads();
    int o = t;
    float acc[16];
#pragma unroll
    for (int r=0;r<16;r++) acc[r]=0.f;
    for (int c=0;c<FF;c++){
        float w = g_W1sumT[c*CC + o];
#pragma unroll
        for (int r=0;r<16;r++) acc[r]=fmaf(sf[r][c], w, acc[r]);
    }
#pragma unroll
    for (int r=0;r<16;r++) g_P[(size_t)(r0+r)*CC + o] = acc[r];
}

// ---------------- Q = tf32(centroid feat) @ W1AT ----------------
__global__ __launch_bounds__(256) void k_qgemm(const float* __restrict__ feat){
    __shared__ float sf[16][FF];
    int r0 = blockIdx.x*16, t = threadIdx.x;
    for (int i=t; i<16*FF; i+=256){
        int rr = r0 + i/FF;
        int b  = rr / SS;
        int cent = g_cent[rr];
        sf[i/FF][i%FF] = to_tf32(feat[(size_t)(b*NN + cent)*FF + (i%FF)]);
    }
    __syncthreads();
    int o = t;
    float acc[16];
#pragma unroll
    for (int r=0;r<16;r++) acc[r]=0.f;
    for (int c=0;c<FF;c++){
        float w = g_W1AT[c*CC + o];
#pragma unroll
        for (int r=0;r<16;r++) acc[r]=fmaf(sf[r][c], w, acc[r]);
    }
#pragma unroll
    for (int r=0;r<16;r++) g_Q[(size_t)(r0+r)*CC + o] = acc[r];
}

// ---------------- BN1 stats ----------------
__global__ __launch_bounds__(256) void k_stats1(const float* __restrict__ b1){
    __shared__ int sg[KK];
    int q = blockIdx.x, t = threadIdx.x, b = q/SS;
    if (t < KK) sg[t] = g_group[q*KK + t];
    __syncthreads();
    int o = t;
    float base = b1[o] - g_Q[(size_t)q*CC + o];
    float sum=0.f, sq=0.f;
    for (int k=0;k<KK;k++){
        float h = g_P[(size_t)(b*NN + sg[k])*CC + o] + base;
        sum += h; sq = fmaf(h,h,sq);
    }
    atomicAdd(&g_sum1[o], sum);
    atomicAdd(&g_sq1[o],  sq);
}

// ---------------- layer2 GEMM via mma.sync tf32 ----------------
#define ASTR 36
extern __shared__ float dyn_smem[];
__global__ __launch_bounds__(256, 1) void k_gemm2m(const float* __restrict__ b1,
                                                   const float* __restrict__ gamma1,
                                                   const float* __restrict__ beta1,
                                                   const float* __restrict__ b2){
    __shared__ float a_s[CC];
    __shared__ float d_s[2*CC];
    __shared__ int   s_nbr[128];

    float* As = dyn_smem;             // [128][ASTR]
    float* Bs = dyn_smem + 128*ASTR;  // [256][ASTR]

    int t = threadIdx.x;
    int bid = blockIdx.x;
    int q0 = 2*bid;
    int batch = q0 >> 10;

    if (t < 128) s_nbr[t] = g_group[bid*128 + t];
    {
        int c = t;
        float mean = g_sum1[c]*(1.0f/MTOT);
        float var  = g_sq1[c]*(1.0f/MTOT) - mean*mean;
        float a    = gamma1[c]*rsqrtf(var + EPSF);
        float ccv  = beta1[c] - mean*a;
        a_s[c] = a;
        d_s[c]    = fmaf(a, b1[c] - g_Q[(size_t)q0*CC + c], ccv);
        d_s[CC+c] = fmaf(a, b1[c] - g_Q[(size_t)(q0+1)*CC + c], ccv);
    }

    int lane = t & 31, wid = t >> 5;
    int warpM = wid >> 2, warpN = wid & 3;
    int r0 = warpM*64, n0 = warpN*64;
    int g = lane >> 2, tig = lane & 3;

    float acc[4][8][4];
#pragma unroll
    for (int mt=0;mt<4;mt++)
#pragma unroll
        for (int nt=0;nt<8;nt++)
#pragma unroll
            for (int i=0;i<4;i++) acc[mt][nt][i]=0.f;

    const uint32_t* Ab = (const uint32_t*)As + (r0+g)*ASTR + tig;
    const uint32_t* Bb = (const uint32_t*)Bs + (n0+g)*ASTR + tig;

    int am = t >> 1;
    int aj0 = (t & 1) * 16;
    int agrp = am >> 6;
    const float* Pr_base = g_P + ((size_t)(batch*NN)) * CC;
    __syncthreads();
    int nbr = s_nbr[am];
    const float* Pr = Pr_base + (size_t)nbr*CC;

#pragma unroll 1
    for (int kc=0; kc<8; kc++){
        if (kc > 0) __syncthreads();
        {
            const float* dv = d_s + agrp*CC + kc*32 + aj0;
            const float* av = a_s + kc*32 + aj0;
            const float* pr = Pr + kc*32 + aj0;
            float* arow = As + am*ASTR + aj0;
#pragma unroll
            for (int i=0;i<4;i++){
                float4 p = *(const float4*)(pr + 4*i);
                float4 v;
                v.x = to_tf32(fmaxf(fmaf(av[4*i+0], p.x, dv[4*i+0]), 0.f));
                v.y = to_tf32(fmaxf(fmaf(av[4*i+1], p.y, dv[4*i+1]), 0.f));
                v.z = to_tf32(fmaxf(fmaf(av[4*i+2], p.z, dv[4*i+2]), 0.f));
                v.w = to_tf32(fmaxf(fmaf(av[4*i+3], p.w, dv[4*i+3]), 0.f));
                *(float4*)(arow + 4*i) = v;
            }
        }
        {
            const float* wr = g_W2rt + (size_t)t*CC + kc*32;
            float* brow = Bs + t*ASTR;
#pragma unroll
            for (int i=0;i<8;i++)
                *(float4*)(brow + 4*i) = *(const float4*)(wr + 4*i);
        }
        __syncthreads();
#pragma unroll
        for (int kk=0; kk<4; kk++){
            int kb = kk*8;
            uint32_t af[4][4];
#pragma unroll
            for (int mt=0;mt<4;mt++){
                af[mt][0] = Ab[(mt*16    )*ASTR + kb];
                af[mt][1] = Ab[(mt*16 + 8)*ASTR + kb];
                af[mt][2] = Ab[(mt*16    )*ASTR + kb + 4];
                af[mt][3] = Ab[(mt*16 + 8)*ASTR + kb + 4];
            }
            uint32_t bf[8][2];
#pragma unroll
            for (int nt=0;nt<8;nt++){
                bf[nt][0] = Bb[(nt*8)*ASTR + kb];
                bf[nt][1] = Bb[(nt*8)*ASTR + kb + 4];
            }
#pragma unroll
            for (int mt=0;mt<4;mt++){
#pragma unroll
                for (int nt=0;nt<8;nt++){
                    asm volatile(
                        "mma.sync.aligned.m16n8k8.row.col.f32.tf32.tf32.f32 "
                        "{%0,%1,%2,%3}, {%4,%5,%6,%7}, {%8,%9}, {%0,%1,%2,%3};"
                        : "+f"(acc[mt][nt][0]), "+f"(acc[mt][nt][1]),
                          "+f"(acc[mt][nt][2]), "+f"(acc[mt][nt][3])
                        : "r"(af[mt][0]), "r"(af[mt][1]), "r"(af[mt][2]), "r"(af[mt][3]),
                          "r"(bf[nt][0]), "r"(bf[nt][1]));
                }
            }
        }
    }

    int q = q0 + warpM;
#pragma unroll
    for (int nt=0; nt<8; nt++){
#pragma unroll
        for (int hc=0; hc<2; hc++){
            int col = n0 + nt*8 + 2*tig + hc;
            float bias = __ldg(&b2[col]);
            float mx=-3.402823466e38f, mn=3.402823466e38f, sum=0.f, sq=0.f;
#pragma unroll
            for (int mt=0;mt<4;mt++){
                float h0 = acc[mt][nt][hc]   + bias;
                float h1 = acc[mt][nt][2+hc] + bias;
                mx=fmaxf(mx,fmaxf(h0,h1)); mn=fminf(mn,fminf(h0,h1));
                sum += h0 + h1; sq = fmaf(h0,h0,sq); sq = fmaf(h1,h1,sq);
            }
#pragma unroll
            for (int off=4; off<=16; off<<=1){
                mx  = fmaxf(mx,  __shfl_xor_sync(0xffffffffu, mx,  off));
                mn  = fminf(mn,  __shfl_xor_sync(0xffffffffu, mn,  off));
                sum = sum +      __shfl_xor_sync(0xffffffffu, sum, off);
                sq  = sq +       __shfl_xor_sync(0xffffffffu, sq,  off);
            }
            if (g == 0){
                g_mx[(size_t)q*CC + col] = mx;
                g_mn[(size_t)q*CC + col] = mn;
                atomicAdd(&g_sum2[col], sum);
                atomicAdd(&g_sq2[col],  sq);
            }
        }
    }
}

// ---------------- BN2 + ReLU + maxpool + outputs ----------------
__global__ __launch_bounds__(256) void k_out(const float* __restrict__ pos,
                                             const float* __restrict__ gamma2,
                                             const float* __restrict__ beta2,
                                             float* __restrict__ out){
    int q = blockIdx.x, t = threadIdx.x, b = q/SS;
    int o = t;
    float mean = g_sum2[o]*(1.0f/MTOT);
    float var  = g_sq2[o]*(1.0f/MTOT) - mean*mean;
    float a    = gamma2[o]*rsqrtf(var + EPSF);
    float cc   = beta2[o] - mean*a;
    float v = (a>=0.f) ? fmaf(a, g_mx[(size_t)q*CC+o], cc)
                       : fmaf(a, g_mn[(size_t)q*CC+o], cc);
    out[(size_t)BB*SS*3 + (size_t)q*CC + o] = fmaxf(v, 0.f);
    if (t < 3){
        int cent = g_cent[q];
        out[(size_t)q*3 + t] = pos[(size_t)(b*NN + cent)*3 + t];
    }
}

// ---------------- launch ----------------
extern "C" void kernel_launch(void* const* d_in, const int* in_sizes, int n_in,
                              void* d_out, int out_size){
    const float* pos    = (const float*)d_in[0];
    const float* feat   = (const float*)d_in[1];
    const float* W1     = (const float*)d_in[2];
    const float* b1     = (const float*)d_in[3];
    const float* gamma1 = (const float*)d_in[4];
    const float* beta1  = (const float*)d_in[5];
    const float* W2     = (const float*)d_in[6];
    const float* b2     = (const float*)d_in[7];
    const float* gamma2 = (const float*)d_in[8];
    const float* beta2  = (const float*)d_in[9];
    float* out = (float*)d_out;

    const int gemm2_smem = (128 + 256) * ASTR * sizeof(float);  // 55296 B
    cudaFuncSetAttribute(k_gemm2m, cudaFuncAttributeMaxDynamicSharedMemorySize, gemm2_smem);

    k_prep  <<<256, 256>>>(W1, W2);
    k_pgemm <<<512, 256>>>(feat, 0);      // launch 2
    k_pgemm <<<512, 256>>>(feat, 512);    // launch 3
    k_fps   <<<BB, 256>>>(pos);           // launch 4 -> profiled slot
    k_knn   <<<BB*SS, 128>>>(pos);
    k_qgemm <<<(BB*SS)/16, 256>>>(feat);
    k_stats1<<<BB*SS, 256>>>(b1);
    k_gemm2m<<<BB*SS/2, 256, gemm2_smem>>>(b1, gamma1, beta1, b2);
    k_out   <<<BB*SS, 256>>>(pos, gamma2, beta2, out);
}

// round 7
// speedup vs baseline: 2.1374x; 1.1710x over previous
#include <cuda_runtime.h>
#include <cuda_bf16.h>
#include <math.h>
#include <stdint.h>

#define BB 4
#define NN 4096
#define FF 128
#define SS 1024
#define KK 64
#define CC 256
#define MTOT (BB*SS*KK)
#define EPSF 1e-5f

// ---------------- device scratch ----------------
__device__ int   g_cent[BB*SS];
__device__ int   g_group[BB*SS*KK];
__device__ float g_P[BB*NN*CC];
__device__ float g_Q[BB*SS*CC];
__device__ float g_W1sumT[FF*CC];
__device__ float g_W1AT[FF*CC];
__device__ float g_W2rt[CC*CC];
__device__ float g_sum1[CC], g_sq1[CC], g_sum2[CC], g_sq2[CC];
__device__ float g_mx[BB*SS*CC], g_mn[BB*SS*CC];

__device__ __forceinline__ float to_tf32(float x){
    unsigned u;
    asm("cvt.rna.tf32.f32 %0, %1;" : "=r"(u) : "f"(x));
    return __uint_as_float(u);
}
// packed f32x2 helpers (per-component rounding == scalar FADD/FMUL/FFMA)
__device__ __forceinline__ unsigned long long pk2(float lo, float hi){
    unsigned long long r;
    asm("mov.b64 %0, {%1,%2};" : "=l"(r) : "f"(lo), "f"(hi));
    return r;
}
__device__ __forceinline__ void upk2(unsigned long long v, float& lo, float& hi){
    asm("mov.b64 {%0,%1}, %2;" : "=f"(lo), "=f"(hi) : "l"(v));
}
__device__ __forceinline__ unsigned long long add2(unsigned long long a, unsigned long long b){
    unsigned long long r; asm("add.rn.f32x2 %0,%1,%2;" : "=l"(r) : "l"(a), "l"(b)); return r;
}
__device__ __forceinline__ unsigned long long mul2(unsigned long long a, unsigned long long b){
    unsigned long long r; asm("mul.rn.f32x2 %0,%1,%2;" : "=l"(r) : "l"(a), "l"(b)); return r;
}
__device__ __forceinline__ unsigned long long fma2(unsigned long long a, unsigned long long b, unsigned long long c){
    unsigned long long r; asm("fma.rn.f32x2 %0,%1,%2,%3;" : "=l"(r) : "l"(a), "l"(b), "l"(c)); return r;
}

// ---------------- prep ----------------
__global__ void k_prep(const float* __restrict__ W1, const float* __restrict__ W2){
    int idx = blockIdx.x*256 + threadIdx.x;
    if (idx < FF*CC){
        int c = idx / CC, o = idx % CC;
        float a = to_tf32(W1[o*(2*FF)+c]);
        float bwt = to_tf32(W1[o*(2*FF)+FF+c]);
        g_W1sumT[idx] = a + bwt;
        g_W1AT[idx]   = a;
    }
    if (idx < CC*CC){
        g_W2rt[idx] = to_tf32(W2[idx]);
    }
    if (idx < CC){
        g_sum1[idx]=0.f; g_sq1[idx]=0.f; g_sum2[idx]=0.f; g_sq2[idx]=0.f;
    }
}

// ---------------- FPS body (blocks 0..3 of mega1) ----------------
__device__ void fps_body(const float* __restrict__ pos, int b){
    __shared__ unsigned swred[2][8];
    __shared__ int      s_sel[SS];
    __shared__ unsigned s_mask[NN/32];
    int t = threadIdx.x;
    const float* bp = pos + (size_t)b*NN*3;

    for (int i=t; i<SS; i+=256) s_sel[i] = 0x7fffffff;
    if (t==0) s_sel[0] = 0;

    unsigned long long px2[8], py2[8], pz2[8];
    float dd[16];
    float qx=bp[0], qy=bp[1], qz=bp[2];
    float vmaxf = 0.f;
#pragma unroll
    for (int jp=0;jp<8;jp++){
        int i0 = t + 256*(2*jp), i1 = t + 256*(2*jp+1);
        float x0=bp[3*i0], y0=bp[3*i0+1], z0=bp[3*i0+2];
        float x1=bp[3*i1], y1=bp[3*i1+1], z1=bp[3*i1+2];
        px2[jp]=pk2(x0,x1); py2[jp]=pk2(y0,y1); pz2[jp]=pk2(z0,z1);
        float dx0=x0-qx, dy0=y0-qy, dz0=z0-qz;
        float dx1=x1-qx, dy1=y1-qy, dz1=z1-qz;
        dd[2*jp]   = dx0*dx0 + dy0*dy0 + dz0*dz0;
        dd[2*jp+1] = dx1*dx1 + dy1*dy1 + dz1*dz1;
        vmaxf = fmaxf(vmaxf, fmaxf(dd[2*jp], dd[2*jp+1]));
    }
    __syncthreads();

    int wid = t >> 5;
#pragma unroll 1
    for (int it=1; it<SS; it++){
        unsigned ub = __float_as_uint(vmaxf);            // dists >= 0: bits order-monotone
        unsigned rv = __reduce_max_sync(0xffffffffu, ub);
        if ((t&31)==0) swred[it&1][wid] = rv;
        __syncthreads();
        unsigned g0 = swred[it&1][0];
#pragma unroll
        for (int w=1;w<8;w++){ unsigned e=swred[it&1][w]; g0 = (e>g0)?e:g0; }
        if (ub == g0){                                   // this thread holds a global-max element
            int idx = 0x7fffffff;
#pragma unroll
            for (int j=15;j>=0;j--)
                if (__float_as_uint(dd[j]) == g0) idx = t + 256*j;   // ends at smallest j
            atomicMin(&s_sel[it], idx);
        }
        __syncthreads();
        int nxt = s_sel[it];
        float cx=__ldg(bp+3*nxt), cy=__ldg(bp+3*nxt+1), cz=__ldg(bp+3*nxt+2);
        unsigned long long ncx=pk2(-cx,-cx), ncy=pk2(-cy,-cy), ncz=pk2(-cz,-cz);
        float nv = 0.f;
#pragma unroll
        for (int jp=0;jp<8;jp++){
            unsigned long long dx2=add2(px2[jp],ncx);
            unsigned long long dy2=add2(py2[jp],ncy);
            unsigned long long dz2=add2(pz2[jp],ncz);
            unsigned long long d2 = mul2(dx2,dx2);
            d2 = fma2(dy2,dy2,d2);
            d2 = fma2(dz2,dz2,d2);
            float dlo,dhi; upk2(d2,dlo,dhi);
            float a = fminf(dd[2*jp],   dlo);
            float c = fminf(dd[2*jp+1], dhi);
            dd[2*jp]=a; dd[2*jp+1]=c;
            nv = fmaxf(nv, fmaxf(a,c));
        }
        vmaxf = nv;
    }
    __syncthreads();
    // sort selected indices ascending via bitmask ranks
    if (t < NN/32) s_mask[t]=0u;
    __syncthreads();
    for (int i=t; i<SS; i+=256) atomicOr(&s_mask[s_sel[i]>>5], 1u<<(s_sel[i]&31));
    __syncthreads();
    for (int i=t; i<SS; i+=256){
        int idx=s_sel[i];
        int w=idx>>5, r=0;
        for (int ww=0; ww<w; ww++) r += __popc(s_mask[ww]);
        r += __popc(s_mask[w] & ((1u<<(idx&31))-1u));
        g_cent[b*SS + r] = idx;
    }
}

// ---------------- pgemm body (blocks 4.. of mega1) ----------------
__device__ void pgemm_body(const float* __restrict__ feat, int blk){
    __shared__ float sf[16][FF];
    int r0 = blk*16, t = threadIdx.x;
    for (int i=t; i<16*FF; i+=256)
        sf[i/FF][i%FF] = to_tf32(feat[(size_t)(r0 + i/FF)*FF + (i%FF)]);
    __syncthreads();
    int o = t;
    float acc[16];
#pragma unroll
    for (int r=0;r<16;r++) acc[r]=0.f;
    for (int c=0;c<FF;c++){
        float w = g_W1sumT[c*CC + o];
#pragma unroll
        for (int r=0;r<16;r++) acc[r]=fmaf(sf[r][c], w, acc[r]);
    }
#pragma unroll
    for (int r=0;r<16;r++) g_P[(size_t)(r0+r)*CC + o] = acc[r];
}

// ---------------- mega1: FPS (4 blocks) || pgemm (1024 blocks) ----------------
__global__ __launch_bounds__(256) void k_mega1(const float* __restrict__ pos,
                                               const float* __restrict__ feat){
    if (blockIdx.x < 4) fps_body(pos, blockIdx.x);
    else                pgemm_body(feat, blockIdx.x - 4);
}

// ---------------- KNN (exact fp32 radix select, 128 threads) ----------------
__global__ __launch_bounds__(128) void k_knn(const float* __restrict__ pos){
    __shared__ unsigned sbits[NN];
    __shared__ int shist[256];
    __shared__ unsigned s_prefix;
    __shared__ int s_want, s_cnt, s_eqcnt;
    __shared__ int s_eq[128];
    int q = blockIdx.x, t = threadIdx.x;
    int b = q / SS;
    int c = g_cent[q];
    const float* bp = pos + (size_t)b*NN*3;
    float qx=bp[3*c], qy=bp[3*c+1], qz=bp[3*c+2];
    float qq = __fadd_rn(__fadd_rn(__fmul_rn(qx,qx), __fmul_rn(qy,qy)), __fmul_rn(qz,qz));

    for (int i=t; i<NN; i+=128){
        float x=bp[3*i], y=bp[3*i+1], z=bp[3*i+2];
        float pp = __fadd_rn(__fadd_rn(__fmul_rn(x,x), __fmul_rn(y,y)), __fmul_rn(z,z));
        float dot = __fadd_rn(__fadd_rn(__fmul_rn(qx,x), __fmul_rn(qy,y)), __fmul_rn(qz,z));
        float d = __fadd_rn(__fadd_rn(__fmul_rn(-2.0f, dot), qq), pp);
        unsigned u = __float_as_uint(d);
        u = (u & 0x80000000u) ? ~u : (u | 0x80000000u);
        sbits[i] = u;
    }
    if (t==0){ s_prefix=0u; s_want=KK; s_cnt=0; s_eqcnt=0; }
    __syncthreads();

    for (int pass=0; pass<4; pass++){
        int shift = 24 - 8*pass;
        for (int i=t; i<256; i+=128) shist[i]=0;
        __syncthreads();
        unsigned pref = s_prefix;
        for (int i=t; i<NN; i+=128){
            unsigned u = sbits[i];
            bool m = (pass==0) || ((u >> (shift+8)) == pref);
            if (m) atomicAdd(&shist[(u>>shift)&0xFFu], 1);
        }
        __syncthreads();
        if (t==0){
            int want=s_want, cum=0, bin;
            for (bin=0; bin<256; bin++){
                int h=shist[bin];
                if (cum+h >= want) break;
                cum += h;
            }
            s_want = want - cum;
            s_prefix = (s_prefix<<8) | (unsigned)bin;
        }
        __syncthreads();
    }
    unsigned T = s_prefix;
    for (int i=t; i<NN; i+=128){
        unsigned u = sbits[i];
        if (u < T){
            int p = atomicAdd(&s_cnt,1);
            g_group[q*KK + p] = i;
        } else if (u == T){
            int p = atomicAdd(&s_eqcnt,1);
            if (p < 128) s_eq[p] = i;
        }
    }
    __syncthreads();
    if (t==0){
        int base = s_cnt;
        int nd   = KK - base;
        int ec   = s_eqcnt;
        if (ec <= 128){
            for (int r=0; r<nd; r++){
                int mi=r;
                for (int j=r+1; j<ec; j++) if (s_eq[j] < s_eq[mi]) mi=j;
                int tmp=s_eq[r]; s_eq[r]=s_eq[mi]; s_eq[mi]=tmp;
                g_group[q*KK + base + r] = s_eq[r];
            }
        } else {
            int w=nd, p=base;
            for (int i=0; i<NN && w>0; i++)
                if (sbits[i]==T){ g_group[q*KK + p++] = i; w--; }
        }
    }
}

// ---------------- Q = tf32(centroid feat) @ W1AT ----------------
__global__ __launch_bounds__(256) void k_qgemm(const float* __restrict__ feat){
    __shared__ float sf[16][FF];
    int r0 = blockIdx.x*16, t = threadIdx.x;
    for (int i=t; i<16*FF; i+=256){
        int rr = r0 + i/FF;
        int b  = rr / SS;
        int cent = g_cent[rr];
        sf[i/FF][i%FF] = to_tf32(feat[(size_t)(b*NN + cent)*FF + (i%FF)]);
    }
    __syncthreads();
    int o = t;
    float acc[16];
#pragma unroll
    for (int r=0;r<16;r++) acc[r]=0.f;
    for (int c=0;c<FF;c++){
        float w = g_W1AT[c*CC + o];
#pragma unroll
        for (int r=0;r<16;r++) acc[r]=fmaf(sf[r][c], w, acc[r]);
    }
#pragma unroll
    for (int r=0;r<16;r++) g_Q[(size_t)(r0+r)*CC + o] = acc[r];
}

// ---------------- BN1 stats ----------------
__global__ __launch_bounds__(256) void k_stats1(const float* __restrict__ b1){
    __shared__ int sg[KK];
    int q = blockIdx.x, t = threadIdx.x, b = q/SS;
    if (t < KK) sg[t] = g_group[q*KK + t];
    __syncthreads();
    int o = t;
    float base = b1[o] - g_Q[(size_t)q*CC + o];
    float sum=0.f, sq=0.f;
    for (int k=0;k<KK;k++){
        float h = g_P[(size_t)(b*NN + sg[k])*CC + o] + base;
        sum += h; sq = fmaf(h,h,sq);
    }
    atomicAdd(&g_sum1[o], sum);
    atomicAdd(&g_sq1[o],  sq);
}

// ---------------- layer2 GEMM via mma.sync tf32 ----------------
#define ASTR 36
extern __shared__ float dyn_smem[];
__global__ __launch_bounds__(256, 1) void k_gemm2m(const float* __restrict__ b1,
                                                   const float* __restrict__ gamma1,
                                                   const float* __restrict__ beta1,
                                                   const float* __restrict__ b2){
    __shared__ float a_s[CC];
    __shared__ float d_s[2*CC];
    __shared__ int   s_nbr[128];

    float* As = dyn_smem;             // [128][ASTR]
    float* Bs = dyn_smem + 128*ASTR;  // [256][ASTR]

    int t = threadIdx.x;
    int bid = blockIdx.x;
    int q0 = 2*bid;
    int batch = q0 >> 10;

    if (t < 128) s_nbr[t] = g_group[bid*128 + t];
    {
        int c = t;
        float mean = g_sum1[c]*(1.0f/MTOT);
        float var  = g_sq1[c]*(1.0f/MTOT) - mean*mean;
        float a    = gamma1[c]*rsqrtf(var + EPSF);
        float ccv  = beta1[c] - mean*a;
        a_s[c] = a;
        d_s[c]    = fmaf(a, b1[c] - g_Q[(size_t)q0*CC + c], ccv);
        d_s[CC+c] = fmaf(a, b1[c] - g_Q[(size_t)(q0+1)*CC + c], ccv);
    }

    int lane = t & 31, wid = t >> 5;
    int warpM = wid >> 2, warpN = wid & 3;
    int r0 = warpM*64, n0 = warpN*64;
    int g = lane >> 2, tig = lane & 3;

    float acc[4][8][4];
#pragma unroll
    for (int mt=0;mt<4;mt++)
#pragma unroll
        for (int nt=0;nt<8;nt++)
#pragma unroll
            for (int i=0;i<4;i++) acc[mt][nt][i]=0.f;

    const uint32_t* Ab = (const uint32_t*)As + (r0+g)*ASTR + tig;
    const uint32_t* Bb = (const uint32_t*)Bs + (n0+g)*ASTR + tig;

    int am = t >> 1;
    int aj0 = (t & 1) * 16;
    int agrp = am >> 6;
    const float* Pr_base = g_P + ((size_t)(batch*NN)) * CC;
    __syncthreads();
    int nbr = s_nbr[am];
    const float* Pr = Pr_base + (size_t)nbr*CC;

#pragma unroll 1
    for (int kc=0; kc<8; kc++){
        if (kc > 0) __syncthreads();
        {
            const float* dv = d_s + agrp*CC + kc*32 + aj0;
            const float* av = a_s + kc*32 + aj0;
            const float* pr = Pr + kc*32 + aj0;
            float* arow = As + am*ASTR + aj0;
#pragma unroll
            for (int i=0;i<4;i++){
                float4 p = *(const float4*)(pr + 4*i);
                float4 v;
                v.x = to_tf32(fmaxf(fmaf(av[4*i+0], p.x, dv[4*i+0]), 0.f));
                v.y = to_tf32(fmaxf(fmaf(av[4*i+1], p.y, dv[4*i+1]), 0.f));
                v.z = to_tf32(fmaxf(fmaf(av[4*i+2], p.z, dv[4*i+2]), 0.f));
                v.w = to_tf32(fmaxf(fmaf(av[4*i+3], p.w, dv[4*i+3]), 0.f));
                *(float4*)(arow + 4*i) = v;
            }
        }
        {
            const float* wr = g_W2rt + (size_t)t*CC + kc*32;
            float* brow = Bs + t*ASTR;
#pragma unroll
            for (int i=0;i<8;i++)
                *(float4*)(brow + 4*i) = *(const float4*)(wr + 4*i);
        }
        __syncthreads();
#pragma unroll
        for (int kk=0; kk<4; kk++){
            int kb = kk*8;
            uint32_t af[4][4];
#pragma unroll
            for (int mt=0;mt<4;mt++){
                af[mt][0] = Ab[(mt*16    )*ASTR + kb];
                af[mt][1] = Ab[(mt*16 + 8)*ASTR + kb];
                af[mt][2] = Ab[(mt*16    )*ASTR + kb + 4];
                af[mt][3] = Ab[(mt*16 + 8)*ASTR + kb + 4];
            }
            uint32_t bf[8][2];
#pragma unroll
            for (int nt=0;nt<8;nt++){
                bf[nt][0] = Bb[(nt*8)*ASTR + kb];
                bf[nt][1] = Bb[(nt*8)*ASTR + kb + 4];
            }
#pragma unroll
            for (int mt=0;mt<4;mt++){
#pragma unroll
                for (int nt=0;nt<8;nt++){
                    asm volatile(
                        "mma.sync.aligned.m16n8k8.row.col.f32.tf32.tf32.f32 "
                        "{%0,%1,%2,%3}, {%4,%5,%6,%7}, {%8,%9}, {%0,%1,%2,%3};"
                        : "+f"(acc[mt][nt][0]), "+f"(acc[mt][nt][1]),
                          "+f"(acc[mt][nt][2]), "+f"(acc[mt][nt][3])
                        : "r"(af[mt][0]), "r"(af[mt][1]), "r"(af[mt][2]), "r"(af[mt][3]),
                          "r"(bf[nt][0]), "r"(bf[nt][1]));
                }
            }
        }
    }

    int q = q0 + warpM;
#pragma unroll
    for (int nt=0; nt<8; nt++){
#pragma unroll
        for (int hc=0; hc<2; hc++){
            int col = n0 + nt*8 + 2*tig + hc;
            float bias = __ldg(&b2[col]);
            float mx=-3.402823466e38f, mn=3.402823466e38f, sum=0.f, sq=0.f;
#pragma unroll
            for (int mt=0;mt<4;mt++){
                float h0 = acc[mt][nt][hc]   + bias;
                float h1 = acc[mt][nt][2+hc] + bias;
                mx=fmaxf(mx,fmaxf(h0,h1)); mn=fminf(mn,fminf(h0,h1));
                sum += h0 + h1; sq = fmaf(h0,h0,sq); sq = fmaf(h1,h1,sq);
            }
#pragma unroll
            for (int off=4; off<=16; off<<=1){
                mx  = fmaxf(mx,  __shfl_xor_sync(0xffffffffu, mx,  off));
                mn  = fminf(mn,  __shfl_xor_sync(0xffffffffu, mn,  off));
                sum = sum +      __shfl_xor_sync(0xffffffffu, sum, off);
                sq  = sq +       __shfl_xor_sync(0xffffffffu, sq,  off);
            }
            if (g == 0){
                g_mx[(size_t)q*CC + col] = mx;
                g_mn[(size_t)q*CC + col] = mn;
                atomicAdd(&g_sum2[col], sum);
                atomicAdd(&g_sq2[col],  sq);
            }
        }
    }
}

// ---------------- BN2 + ReLU + maxpool + outputs ----------------
__global__ __launch_bounds__(256) void k_out(const float* __restrict__ pos,
                                             const float* __restrict__ gamma2,
                                             const float* __restrict__ beta2,
                                             float* __restrict__ out){
    int q = blockIdx.x, t = threadIdx.x, b = q/SS;
    int o = t;
    float mean = g_sum2[o]*(1.0f/MTOT);
    float var  = g_sq2[o]*(1.0f/MTOT) - mean*mean;
    float a    = gamma2[o]*rsqrtf(var + EPSF);
    float cc   = beta2[o] - mean*a;
    float v = (a>=0.f) ? fmaf(a, g_mx[(size_t)q*CC+o], cc)
                       : fmaf(a, g_mn[(size_t)q*CC+o], cc);
    out[(size_t)BB*SS*3 + (size_t)q*CC + o] = fmaxf(v, 0.f);
    if (t < 3){
        int cent = g_cent[q];
        out[(size_t)q*3 + t] = pos[(size_t)(b*NN + cent)*3 + t];
    }
}

// ---------------- launch ----------------
extern "C" void kernel_launch(void* const* d_in, const int* in_sizes, int n_in,
                              void* d_out, int out_size){
    const float* pos    = (const float*)d_in[0];
    const float* feat   = (const float*)d_in[1];
    const float* W1     = (const float*)d_in[2];
    const float* b1     = (const float*)d_in[3];
    const float* gamma1 = (const float*)d_in[4];
    const float* beta1  = (const float*)d_in[5];
    const float* W2     = (const float*)d_in[6];
    const float* b2     = (const float*)d_in[7];
    const float* gamma2 = (const float*)d_in[8];
    const float* beta2  = (const float*)d_in[9];
    float* out = (float*)d_out;

    const int gemm2_smem = (128 + 256) * ASTR * sizeof(float);  // 55296 B
    cudaFuncSetAttribute(k_gemm2m, cudaFuncAttributeMaxDynamicSharedMemorySize, gemm2_smem);

    k_prep  <<<256, 256>>>(W1, W2);                // 1
    k_mega1 <<<4 + (BB*NN)/16, 256>>>(pos, feat);  // 2: FPS || pgemm
    k_qgemm <<<(BB*SS)/16, 256>>>(feat);           // 3
    k_knn   <<<BB*SS, 128>>>(pos);                 // 4 -> profiled slot
    k_stats1<<<BB*SS, 256>>>(b1);                  // 5
    k_gemm2m<<<BB*SS/2, 256, gemm2_smem>>>(b1, gamma1, beta1, b2);  // 6
    k_out   <<<BB*SS, 256>>>(pos, gamma2, beta2, out);              // 7
}